// round 1
// baseline (speedup 1.0000x reference)
#include <cuda_runtime.h>

#define BATCH   512
#define CIN     2048
#define OFEAT   64
#define KDIM    16
#define MCOLS   (OFEAT * KDIM)      // 1024
#define OUTW    (CIN + OFEAT)       // 2112

// Scratch for m = x @ T  (512 x 1024 fp32 = 2 MB, L2-resident)
__device__ float g_m[BATCH * MCOLS];

// ---------------------------------------------------------------------------
// GEMM: m[B, 1024] = x[B, 2048] @ T[2048, 1024]   (fp32, tiled)
// BM=BN=64, BK=16, 256 threads, 4x4 register tile per thread.
// ---------------------------------------------------------------------------
__global__ __launch_bounds__(256) void gemm_kernel(
    const float* __restrict__ x, const float* __restrict__ T, float* __restrict__ m)
{
    __shared__ float As[16][68];   // k-major, padded (68 % 4 == 0 keeps float4 align)
    __shared__ float Bs[16][64];   // k-major

    const int bn = blockIdx.x;     // 0..15  (N tiles)
    const int bm = blockIdx.y;     // 0..7   (M tiles)
    const int tid = threadIdx.x;
    const int tx = tid & 15;       // 0..15
    const int ty = tid >> 4;       // 0..15

    const int row0 = bm * 64;
    const int col0 = bn * 64;

    // load indices for A: each thread loads one float4 (64 rows x 16 k)
    const int a_row = tid >> 2;          // 0..63
    const int a_k4  = (tid & 3) * 4;     // 0,4,8,12
    // load indices for B: each thread loads one float4 (16 k x 64 cols)
    const int b_k   = tid >> 4;          // 0..15
    const int b_c4  = (tid & 15) * 4;    // 0..60

    float acc[4][4];
#pragma unroll
    for (int i = 0; i < 4; ++i)
#pragma unroll
        for (int j = 0; j < 4; ++j) acc[i][j] = 0.0f;

    for (int k0 = 0; k0 < CIN; k0 += 16) {
        // stage A (transposed to k-major)
        float4 av = *(const float4*)&x[(row0 + a_row) * CIN + k0 + a_k4];
        As[a_k4 + 0][a_row] = av.x;
        As[a_k4 + 1][a_row] = av.y;
        As[a_k4 + 2][a_row] = av.z;
        As[a_k4 + 3][a_row] = av.w;
        // stage B
        *(float4*)&Bs[b_k][b_c4] = *(const float4*)&T[(k0 + b_k) * MCOLS + col0 + b_c4];
        __syncthreads();

#pragma unroll
        for (int kk = 0; kk < 16; ++kk) {
            float4 a = *(const float4*)&As[kk][ty * 4];
            float4 b = *(const float4*)&Bs[kk][tx * 4];
            acc[0][0] += a.x * b.x; acc[0][1] += a.x * b.y; acc[0][2] += a.x * b.z; acc[0][3] += a.x * b.w;
            acc[1][0] += a.y * b.x; acc[1][1] += a.y * b.y; acc[1][2] += a.y * b.z; acc[1][3] += a.y * b.w;
            acc[2][0] += a.z * b.x; acc[2][1] += a.z * b.y; acc[2][2] += a.z * b.z; acc[2][3] += a.z * b.w;
            acc[3][0] += a.w * b.x; acc[3][1] += a.w * b.y; acc[3][2] += a.w * b.z; acc[3][3] += a.w * b.w;
        }
        __syncthreads();
    }

#pragma unroll
    for (int i = 0; i < 4; ++i) {
        float4 v = make_float4(acc[i][0], acc[i][1], acc[i][2], acc[i][3]);
        *(float4*)&m[(row0 + ty * 4 + i) * MCOLS + col0 + tx * 4] = v;
    }
}

// ---------------------------------------------------------------------------
// Pairwise: out[b, 2048+o] = sum_j exp(-sum_k |m[b,o,k] - m[j,o,k]|)
// grid = (4 b-tiles of 128, 64 o), 256 threads: tid = h*128 + r.
// Thread owns row b = bt*128 + r (16 floats in regs); halves split the j range
// of each staged 128-row tile. Shared reads are warp-uniform -> broadcast.
// ---------------------------------------------------------------------------
__global__ __launch_bounds__(256) void pairwise_kernel(
    const float* __restrict__ m, float* __restrict__ out)
{
    __shared__ float sj[128][16];
    __shared__ float partial[128];

    const int o   = blockIdx.y;
    const int bt  = blockIdx.x;
    const int tid = threadIdx.x;
    const int h   = tid >> 7;      // 0/1
    const int r   = tid & 127;
    const int b   = bt * 128 + r;

    const float* vb = &m[b * MCOLS + o * KDIM];
    float4 v0 = *(const float4*)&vb[0];
    float4 v1 = *(const float4*)&vb[4];
    float4 v2 = *(const float4*)&vb[8];
    float4 v3 = *(const float4*)&vb[12];

    float acc = 0.0f;
    const int jr = tid >> 1;
    const int p  = (tid & 1) * 8;

    for (int jt = 0; jt < 4; ++jt) {
        const float* src = &m[(jt * 128 + jr) * MCOLS + o * KDIM + p];
        float4 t0 = *(const float4*)&src[0];
        float4 t1 = *(const float4*)&src[4];
        __syncthreads();   // ensure previous tile fully consumed
        *(float4*)&sj[jr][p]     = t0;
        *(float4*)&sj[jr][p + 4] = t1;
        __syncthreads();

        const int j0 = h * 64;
#pragma unroll 4
        for (int jj = 0; jj < 64; ++jj) {
            const float* s = sj[j0 + jj];
            float4 s0 = *(const float4*)&s[0];
            float4 s1 = *(const float4*)&s[4];
            float4 s2 = *(const float4*)&s[8];
            float4 s3 = *(const float4*)&s[12];
            float d0 = fabsf(v0.x - s0.x) + fabsf(v0.y - s0.y);
            float d1 = fabsf(v0.z - s0.z) + fabsf(v0.w - s0.w);
            float d2 = fabsf(v1.x - s1.x) + fabsf(v1.y - s1.y);
            float d3 = fabsf(v1.z - s1.z) + fabsf(v1.w - s1.w);
            float d4 = fabsf(v2.x - s2.x) + fabsf(v2.y - s2.y);
            float d5 = fabsf(v2.z - s2.z) + fabsf(v2.w - s2.w);
            float d6 = fabsf(v3.x - s3.x) + fabsf(v3.y - s3.y);
            float d7 = fabsf(v3.z - s3.z) + fabsf(v3.w - s3.w);
            float d = ((d0 + d1) + (d2 + d3)) + ((d4 + d5) + (d6 + d7));
            acc += __expf(-d);
        }
    }

    if (h == 1) partial[r] = acc;
    __syncthreads();
    if (h == 0) out[b * OUTW + CIN + o] = acc + partial[r];
}

// ---------------------------------------------------------------------------
// Copy x into out[:, 0:2048]  (float4 vectorized)
// ---------------------------------------------------------------------------
__global__ __launch_bounds__(256) void copy_x_kernel(
    const float* __restrict__ x, float* __restrict__ out)
{
    int i = blockIdx.x * 256 + threadIdx.x;       // over 512*512 float4s
    int row = i >> 9;                             // / 512
    int c4  = i & 511;
    ((float4*)&out[row * OUTW])[c4] = ((const float4*)&x[row * CIN])[c4];
}

extern "C" void kernel_launch(void* const* d_in, const int* in_sizes, int n_in,
                              void* d_out, int out_size)
{
    const float* x = (const float*)d_in[0];
    const float* T = (const float*)d_in[1];
    float* out = (float*)d_out;

    float* m;
    cudaGetSymbolAddress((void**)&m, g_m);

    copy_x_kernel<<<(BATCH * CIN / 4) / 256, 256>>>(x, out);
    gemm_kernel<<<dim3(MCOLS / 64, BATCH / 64), 256>>>(x, T, m);
    pairwise_kernel<<<dim3(BATCH / 128, OFEAT), 256>>>(m, out);
}

// round 2
// speedup vs baseline: 1.9678x; 1.9678x over previous
#include <cuda_runtime.h>
#include <cuda_fp16.h>

#define BATCH   512
#define CIN     2048
#define OFEAT   64
#define KDIM    16
#define MCOLS   1024
#define OUTW    2112

// Scratch for m = x @ T  (512 x 1024 fp32 = 2 MB, L2-resident)
__device__ float g_m[BATCH * MCOLS];

// ---------------------------------------------------------------------------
// GEMM: m[512,1024] = x[512,2048] @ T[2048,1024] using tf32 mma.sync.m16n8k8
// BM=64, BN=64, BK=32, 256 threads (8 warps, warpgrid 2m x 4n, warp tile 32x16)
// Double-buffered cp.async staging. Strides chosen for conflict-free frag LDS
// and 16B cp.async alignment: SA=44 (bank = 12g+c, distinct), SB=72 (8r+g).
// ---------------------------------------------------------------------------
#define SA 44
#define SB 72

__device__ __forceinline__ void cp16(unsigned saddr, const float* g) {
    asm volatile("cp.async.cg.shared.global [%0], [%1], 16;" :: "r"(saddr), "l"(g));
}
#define CP_COMMIT()  asm volatile("cp.async.commit_group;")
#define CP_WAIT(N)   asm volatile("cp.async.wait_group %0;" :: "n"(N))

__device__ __forceinline__ void mma_tf32(float* d, const unsigned* a, const unsigned* b) {
    asm volatile(
        "mma.sync.aligned.m16n8k8.row.col.f32.tf32.tf32.f32 "
        "{%0,%1,%2,%3}, {%4,%5,%6,%7}, {%8,%9}, {%0,%1,%2,%3};\n"
        : "+f"(d[0]), "+f"(d[1]), "+f"(d[2]), "+f"(d[3])
        : "r"(a[0]), "r"(a[1]), "r"(a[2]), "r"(a[3]), "r"(b[0]), "r"(b[1]));
}

__global__ __launch_bounds__(256) void gemm_tf32(
    const float* __restrict__ x, const float* __restrict__ T, float* __restrict__ m)
{
    __shared__ float As[2][64][SA];
    __shared__ float Bs[2][32][SB];

    const int tid  = threadIdx.x;
    const int lane = tid & 31;
    const int wid  = tid >> 5;
    const int wm   = wid & 1;      // 0..1 (m)
    const int wn   = wid >> 1;     // 0..3 (n)
    const int row0 = blockIdx.y * 64;
    const int col0 = blockIdx.x * 64;
    const int g    = lane >> 2;    // 0..7
    const int c    = lane & 3;     // 0..3

    // cp.async thread mapping
    const int a_row = tid >> 3;          // 0..31 (+32 on second)
    const int a_c4  = (tid & 7) * 4;     // 0..28
    const int b_kr  = tid >> 4;          // 0..15 (+16 on second)
    const int b_c4  = (tid & 15) * 4;    // 0..60

    const float* gA = &x[(row0 + a_row) * CIN + a_c4];
    const float* gB = &T[b_kr * MCOLS + col0 + b_c4];

    float d[2][2][4];
#pragma unroll
    for (int i = 0; i < 2; ++i)
#pragma unroll
        for (int j = 0; j < 2; ++j)
#pragma unroll
            for (int k = 0; k < 4; ++k) d[i][j][k] = 0.0f;

    // prologue: panel 0 -> buf 0
    {
        cp16(__cvta_generic_to_shared(&As[0][a_row][a_c4]),      gA);
        cp16(__cvta_generic_to_shared(&As[0][a_row + 32][a_c4]), gA + 32 * CIN);
        cp16(__cvta_generic_to_shared(&Bs[0][b_kr][b_c4]),       gB);
        cp16(__cvta_generic_to_shared(&Bs[0][b_kr + 16][b_c4]),  gB + 16 * MCOLS);
        CP_COMMIT();
    }

    for (int p = 0; p < 64; ++p) {
        const int buf = p & 1;
        if (p < 63) {
            const int k0 = (p + 1) * 32;
            const int nb = (p + 1) & 1;
            cp16(__cvta_generic_to_shared(&As[nb][a_row][a_c4]),      gA + k0);
            cp16(__cvta_generic_to_shared(&As[nb][a_row + 32][a_c4]), gA + 32 * CIN + k0);
            cp16(__cvta_generic_to_shared(&Bs[nb][b_kr][b_c4]),       gB + k0 * MCOLS);
            cp16(__cvta_generic_to_shared(&Bs[nb][b_kr + 16][b_c4]),  gB + (k0 + 16) * MCOLS);
            CP_COMMIT();
            CP_WAIT(1);
        } else {
            CP_WAIT(0);
        }
        __syncthreads();

#pragma unroll
        for (int k8 = 0; k8 < 4; ++k8) {
            const int kb = k8 * 8;
            unsigned a[2][4], b[2][2];
#pragma unroll
            for (int ai = 0; ai < 2; ++ai) {
                const int rb = wm * 32 + ai * 16;
                a[ai][0] = __float_as_uint(As[buf][rb + g][kb + c]);
                a[ai][1] = __float_as_uint(As[buf][rb + g + 8][kb + c]);
                a[ai][2] = __float_as_uint(As[buf][rb + g][kb + c + 4]);
                a[ai][3] = __float_as_uint(As[buf][rb + g + 8][kb + c + 4]);
            }
#pragma unroll
            for (int bi = 0; bi < 2; ++bi) {
                const int cb = wn * 16 + bi * 8;
                b[bi][0] = __float_as_uint(Bs[buf][kb + c][cb + g]);
                b[bi][1] = __float_as_uint(Bs[buf][kb + c + 4][cb + g]);
            }
#pragma unroll
            for (int ai = 0; ai < 2; ++ai)
#pragma unroll
                for (int bi = 0; bi < 2; ++bi)
                    mma_tf32(d[ai][bi], a[ai], b[bi]);
        }
        __syncthreads();
    }

    // epilogue
#pragma unroll
    for (int ai = 0; ai < 2; ++ai) {
#pragma unroll
        for (int bi = 0; bi < 2; ++bi) {
            const int row = row0 + wm * 32 + ai * 16 + g;
            const int col = col0 + wn * 16 + bi * 8 + c * 2;
            float2 lo = make_float2(d[ai][bi][0], d[ai][bi][1]);
            float2 hi = make_float2(d[ai][bi][2], d[ai][bi][3]);
            *(float2*)&m[row * MCOLS + col]       = lo;
            *(float2*)&m[(row + 8) * MCOLS + col] = hi;
        }
    }
}

// ---------------------------------------------------------------------------
// Pairwise (fp16x2 packed) + folded x->out copy.
// grid = (8 b-tiles of 64, 64 o), 128 threads. tid = h*64 + r.
// Thread owns row b = bt*64 + r as 8 half2 in regs; halves split each staged
// 128-row j tile. Self term is exact zero (identical rounding both paths).
// ---------------------------------------------------------------------------
__global__ __launch_bounds__(128) void pairwise_kernel(
    const float* __restrict__ m, const float* __restrict__ x, float* __restrict__ out)
{
    __shared__ __half2 sj[128][8];
    __shared__ float partial[64];

    const int o   = blockIdx.y;
    const int bt  = blockIdx.x;
    const int tid = threadIdx.x;
    const int h   = tid >> 6;
    const int r   = tid & 63;
    const int b   = bt * 64 + r;

    // folded copy of x into out[:, 0:2048]: 512 float4 per block
    {
        const int bid = blockIdx.y * 8 + blockIdx.x;   // 0..511
#pragma unroll
        for (int k = 0; k < 4; ++k) {
            int i   = bid * 512 + k * 128 + tid;
            int row = i >> 9;
            int c4  = i & 511;
            ((float4*)&out[row * OUTW])[c4] = ((const float4*)&x[row * CIN])[c4];
        }
    }

    // own row -> 8 half2 regs
    const float* vb = &m[b * MCOLS + o * KDIM];
    float4 f0 = *(const float4*)&vb[0];
    float4 f1 = *(const float4*)&vb[4];
    float4 f2 = *(const float4*)&vb[8];
    float4 f3 = *(const float4*)&vb[12];
    __half2 v[8];
    v[0] = __floats2half2_rn(f0.x, f0.y); v[1] = __floats2half2_rn(f0.z, f0.w);
    v[2] = __floats2half2_rn(f1.x, f1.y); v[3] = __floats2half2_rn(f1.z, f1.w);
    v[4] = __floats2half2_rn(f2.x, f2.y); v[5] = __floats2half2_rn(f2.z, f2.w);
    v[6] = __floats2half2_rn(f3.x, f3.y); v[7] = __floats2half2_rn(f3.z, f3.w);

    float acc = 0.0f;

    for (int jt = 0; jt < 4; ++jt) {
        const float* src = &m[(jt * 128 + tid) * MCOLS + o * KDIM];
        float4 t0 = *(const float4*)&src[0];
        float4 t1 = *(const float4*)&src[4];
        float4 t2 = *(const float4*)&src[8];
        float4 t3 = *(const float4*)&src[12];
        __syncthreads();   // previous tile fully consumed
        __half2* row = sj[tid];
        row[0] = __floats2half2_rn(t0.x, t0.y); row[1] = __floats2half2_rn(t0.z, t0.w);
        row[2] = __floats2half2_rn(t1.x, t1.y); row[3] = __floats2half2_rn(t1.z, t1.w);
        row[4] = __floats2half2_rn(t2.x, t2.y); row[5] = __floats2half2_rn(t2.z, t2.w);
        row[6] = __floats2half2_rn(t3.x, t3.y); row[7] = __floats2half2_rn(t3.z, t3.w);
        __syncthreads();

#pragma unroll 4
        for (int jj = 0; jj < 64; ++jj) {
            const __half2* s = sj[h * 64 + jj];
            __half2 q0 = __habs2(__hsub2(v[0], s[0]));
            __half2 q1 = __habs2(__hsub2(v[1], s[1]));
            __half2 q2 = __habs2(__hsub2(v[2], s[2]));
            __half2 q3 = __habs2(__hsub2(v[3], s[3]));
            __half2 q4 = __habs2(__hsub2(v[4], s[4]));
            __half2 q5 = __habs2(__hsub2(v[5], s[5]));
            __half2 q6 = __habs2(__hsub2(v[6], s[6]));
            __half2 q7 = __habs2(__hsub2(v[7], s[7]));
            __half2 p0 = __hadd2(q0, q1);
            __half2 p1 = __hadd2(q2, q3);
            __half2 p2 = __hadd2(q4, q5);
            __half2 p3 = __hadd2(q6, q7);
            __half2 sm = __hadd2(__hadd2(p0, p1), __hadd2(p2, p3));
            float dist = __low2float(sm) + __high2float(sm);
            acc += __expf(-dist);
        }
    }

    if (h == 1) partial[r] = acc;
    __syncthreads();
    if (h == 0) out[b * OUTW + CIN + o] = acc + partial[r];
}

extern "C" void kernel_launch(void* const* d_in, const int* in_sizes, int n_in,
                              void* d_out, int out_size)
{
    const float* x = (const float*)d_in[0];
    const float* T = (const float*)d_in[1];
    float* out = (float*)d_out;

    float* m;
    cudaGetSymbolAddress((void**)&m, g_m);

    gemm_tf32<<<dim3(MCOLS / 64, BATCH / 64), 256>>>(x, T, m);
    pairwise_kernel<<<dim3(BATCH / 64, OFEAT), 128>>>(m, x, out);
}

// round 3
// speedup vs baseline: 2.8999x; 1.4737x over previous
#include <cuda_runtime.h>
#include <cuda_fp16.h>
#include <cuda_bf16.h>

#define BATCH   512
#define CIN     2048
#define OFEAT   64
#define KDIM    16
#define MCOLS   1024
#define OUTW    2112

// Scratch (device globals; no allocs)
__device__ __nv_bfloat16 g_xh[BATCH * CIN];     // 2 MB
__device__ __nv_bfloat16 g_Th[CIN * MCOLS];     // 4 MB
__device__ __half        g_mh[BATCH * MCOLS];   // 1 MB

// ---------------------------------------------------------------------------
// Prep: copy x -> out[:, :2048], zero out[:, 2048:], convert x,T -> bf16.
// Exactly 794624 work items (float4 granularity); grid 3104 x 256.
// ---------------------------------------------------------------------------
__global__ __launch_bounds__(256) void prep_kernel(
    const float* __restrict__ x, const float* __restrict__ T, float* __restrict__ out)
{
    int id = blockIdx.x * 256 + threadIdx.x;
    if (id < 262144) {                       // x: 512*512 float4
        int row = id >> 9, c4 = id & 511;
        float4 v = ((const float4*)&x[row * CIN])[c4];
        ((float4*)&out[row * OUTW])[c4] = v;
        __nv_bfloat162* dst = (__nv_bfloat162*)&g_xh[row * CIN + c4 * 4];
        dst[0] = __floats2bfloat162_rn(v.x, v.y);
        dst[1] = __floats2bfloat162_rn(v.z, v.w);
    } else if (id < 786432) {                // T: 2048*256 float4
        int i = id - 262144;
        float4 v = ((const float4*)T)[i];
        __nv_bfloat162* dst = (__nv_bfloat162*)&g_Th[i * 4];
        dst[0] = __floats2bfloat162_rn(v.x, v.y);
        dst[1] = __floats2bfloat162_rn(v.z, v.w);
    } else if (id < 794624) {                // zero tail: 512*16 float4
        int i = id - 786432;
        int row = i >> 4, c = i & 15;
        ((float4*)&out[row * OUTW + CIN])[c] = make_float4(0.f, 0.f, 0.f, 0.f);
    }
}

// ---------------------------------------------------------------------------
// GEMM bf16: m[512,1024] = x @ T, mma.m16n8k16, epilogue -> fp16 g_mh.
// BM=64 BN=64 BK=32, 256 thr (8 warps 2m x 4n, warp tile 32x16), dbl-buffered
// cp.async. ldmatrix.x4 frag loads (strides 40/72 halves: conflict-free).
// ---------------------------------------------------------------------------
__device__ __forceinline__ void cp16(unsigned s, const void* g) {
    asm volatile("cp.async.cg.shared.global [%0], [%1], 16;" :: "r"(s), "l"(g));
}
#define CP_COMMIT()  asm volatile("cp.async.commit_group;")
#define CP_WAIT(N)   asm volatile("cp.async.wait_group %0;" :: "n"(N))

__device__ __forceinline__ void ldm_x4(unsigned* r, unsigned addr) {
    asm volatile("ldmatrix.sync.aligned.m8n8.x4.shared.b16 {%0,%1,%2,%3}, [%4];"
        : "=r"(r[0]), "=r"(r[1]), "=r"(r[2]), "=r"(r[3]) : "r"(addr));
}
__device__ __forceinline__ void ldm_x4t(unsigned* r, unsigned addr) {
    asm volatile("ldmatrix.sync.aligned.m8n8.x4.trans.shared.b16 {%0,%1,%2,%3}, [%4];"
        : "=r"(r[0]), "=r"(r[1]), "=r"(r[2]), "=r"(r[3]) : "r"(addr));
}
__device__ __forceinline__ void mma_bf16(float* d, const unsigned* a, const unsigned* b) {
    asm volatile(
        "mma.sync.aligned.m16n8k16.row.col.f32.bf16.bf16.f32 "
        "{%0,%1,%2,%3}, {%4,%5,%6,%7}, {%8,%9}, {%0,%1,%2,%3};\n"
        : "+f"(d[0]), "+f"(d[1]), "+f"(d[2]), "+f"(d[3])
        : "r"(a[0]), "r"(a[1]), "r"(a[2]), "r"(a[3]), "r"(b[0]), "r"(b[1]));
}

__global__ __launch_bounds__(256) void gemm_bf16(__half* __restrict__ mh)
{
    __shared__ __nv_bfloat16 As[2][64][40];   // 80B row stride (16B-mult)
    __shared__ __nv_bfloat16 Bs[2][32][72];   // 144B row stride

    const int tid  = threadIdx.x;
    const int lane = tid & 31;
    const int wid  = tid >> 5;
    const int wm   = wid & 1;
    const int wn   = wid >> 1;
    const int row0 = blockIdx.y * 64;
    const int col0 = blockIdx.x * 64;

    const int aRow = tid >> 2, aC = (tid & 3) * 8;   // 64B / row -> 4 chunks
    const int bRow = tid >> 3, bC = (tid & 7) * 8;   // 128B / row -> 8 chunks

    const __nv_bfloat16* gA = &g_xh[(row0 + aRow) * CIN + aC];
    const __nv_bfloat16* gB = &g_Th[bRow * MCOLS + col0 + bC];

    float d[2][2][4];
#pragma unroll
    for (int i = 0; i < 2; ++i)
#pragma unroll
        for (int j = 0; j < 2; ++j)
#pragma unroll
            for (int k = 0; k < 4; ++k) d[i][j][k] = 0.0f;

    cp16(__cvta_generic_to_shared(&As[0][aRow][aC]), gA);
    cp16(__cvta_generic_to_shared(&Bs[0][bRow][bC]), gB);
    CP_COMMIT();

    for (int p = 0; p < 64; ++p) {
        const int buf = p & 1;
        if (p < 63) {
            const int k0 = (p + 1) * 32;
            const int nb = (p + 1) & 1;
            cp16(__cvta_generic_to_shared(&As[nb][aRow][aC]), gA + k0);
            cp16(__cvta_generic_to_shared(&Bs[nb][bRow][bC]), gB + k0 * MCOLS);
            CP_COMMIT();
            CP_WAIT(1);
        } else {
            CP_WAIT(0);
        }
        __syncthreads();

#pragma unroll
        for (int kk = 0; kk < 32; kk += 16) {
            unsigned a0[4], a1[4], bb[4];
            unsigned adrA0 = __cvta_generic_to_shared(
                &As[buf][wm * 32 + (lane & 15)][kk + (lane >> 4) * 8]);
            unsigned adrA1 = __cvta_generic_to_shared(
                &As[buf][wm * 32 + 16 + (lane & 15)][kk + (lane >> 4) * 8]);
            unsigned adrB = __cvta_generic_to_shared(
                &Bs[buf][kk + (lane & 15)][wn * 16 + (lane >> 4) * 8]);
            ldm_x4(a0, adrA0);
            ldm_x4(a1, adrA1);
            ldm_x4t(bb, adrB);
            mma_bf16(d[0][0], a0, bb);
            mma_bf16(d[0][1], a0, bb + 2);
            mma_bf16(d[1][0], a1, bb);
            mma_bf16(d[1][1], a1, bb + 2);
        }
        __syncthreads();
    }

    // epilogue -> fp16
    const int g = lane >> 2, c = lane & 3;
#pragma unroll
    for (int ai = 0; ai < 2; ++ai)
#pragma unroll
        for (int bi = 0; bi < 2; ++bi) {
            int row = row0 + wm * 32 + ai * 16 + g;
            int col = col0 + wn * 16 + bi * 8 + c * 2;
            *(__half2*)&mh[row * MCOLS + col] =
                __floats2half2_rn(d[ai][bi][0], d[ai][bi][1]);
            *(__half2*)&mh[(row + 8) * MCOLS + col] =
                __floats2half2_rn(d[ai][bi][2], d[ai][bi][3]);
        }
}

// ---------------------------------------------------------------------------
// Pairwise: out[b, 2048+o] += sum_{j in chunk} exp(-L1(m[b,o,:], m[j,o,:]))
// grid (jc=8, bt=4, o=64), 128 thr. Thread owns b = bt*128+tid (8 half2 regs).
// Screen: 4-group sums, triangle inequality; warp-uniform full path.
// ---------------------------------------------------------------------------
__global__ __launch_bounds__(128) void pairwise_kernel(
    const __half* __restrict__ mh, float* __restrict__ out)
{
    __shared__ uint4   sjt[64][2];    // 64 rows x 16 halves
    __shared__ __half2 sg[64][2];     // group sums (G0,G1),(G2,G3)

    const int jc  = blockIdx.x;
    const int bt  = blockIdx.y;
    const int o   = blockIdx.z;
    const int tid = threadIdx.x;
    const int b   = bt * 128 + tid;

    // own row
    const uint4* vp = (const uint4*)&mh[b * MCOLS + o * KDIM];
    uint4 u0 = vp[0], u1 = vp[1];
    __half2 v[8];
    *(uint4*)&v[0] = u0;
    *(uint4*)&v[4] = u1;
    __half2 t01 = __hadd2(v[0], v[1]);
    __half2 t23 = __hadd2(v[2], v[3]);
    __half2 t45 = __hadd2(v[4], v[5]);
    __half2 t67 = __hadd2(v[6], v[7]);
    __half2 vg0 = __halves2half2(__hadd(__low2half(t01), __high2half(t01)),
                                 __hadd(__low2half(t23), __high2half(t23)));
    __half2 vg1 = __halves2half2(__hadd(__low2half(t45), __high2half(t45)),
                                 __hadd(__low2half(t67), __high2half(t67)));

    // stage j-chunk
    if (tid < 64) {
        int j = jc * 64 + tid;
        const uint4* jp = (const uint4*)&mh[j * MCOLS + o * KDIM];
        uint4 w0 = jp[0], w1 = jp[1];
        sjt[tid][0] = w0;
        sjt[tid][1] = w1;
        __half2 s[8];
        *(uint4*)&s[0] = w0;
        *(uint4*)&s[4] = w1;
        __half2 a01 = __hadd2(s[0], s[1]);
        __half2 a23 = __hadd2(s[2], s[3]);
        __half2 a45 = __hadd2(s[4], s[5]);
        __half2 a67 = __hadd2(s[6], s[7]);
        sg[tid][0] = __halves2half2(__hadd(__low2half(a01), __high2half(a01)),
                                    __hadd(__low2half(a23), __high2half(a23)));
        sg[tid][1] = __halves2half2(__hadd(__low2half(a45), __high2half(a45)),
                                    __hadd(__low2half(a67), __high2half(a67)));
    }
    __syncthreads();

    float acc = 0.0f;
#pragma unroll 4
    for (int jj = 0; jj < 64; ++jj) {
        __half2 e0 = __habs2(__hsub2(vg0, sg[jj][0]));
        __half2 e1 = __habs2(__hsub2(vg1, sg[jj][1]));
        __half2 et = __hadd2(e0, e1);
        float screen = __low2float(et) + __high2float(et);
        if (__any_sync(0xffffffffu, screen < 30.0f)) {
            __half2 s[8];
            *(uint4*)&s[0] = sjt[jj][0];
            *(uint4*)&s[4] = sjt[jj][1];
            __half2 q0 = __habs2(__hsub2(v[0], s[0]));
            __half2 q1 = __habs2(__hsub2(v[1], s[1]));
            __half2 q2 = __habs2(__hsub2(v[2], s[2]));
            __half2 q3 = __habs2(__hsub2(v[3], s[3]));
            __half2 q4 = __habs2(__hsub2(v[4], s[4]));
            __half2 q5 = __habs2(__hsub2(v[5], s[5]));
            __half2 q6 = __habs2(__hsub2(v[6], s[6]));
            __half2 q7 = __habs2(__hsub2(v[7], s[7]));
            __half2 sm = __hadd2(__hadd2(__hadd2(q0, q1), __hadd2(q2, q3)),
                                 __hadd2(__hadd2(q4, q5), __hadd2(q6, q7)));
            float dist = __low2float(sm) + __high2float(sm);
            acc += __expf(-dist);
        }
    }

    atomicAdd(&out[b * OUTW + CIN + o], acc);
}

extern "C" void kernel_launch(void* const* d_in, const int* in_sizes, int n_in,
                              void* d_out, int out_size)
{
    const float* x = (const float*)d_in[0];
    const float* T = (const float*)d_in[1];
    float* out = (float*)d_out;

    __half* mh;
    cudaGetSymbolAddress((void**)&mh, g_mh);

    prep_kernel<<<3104, 256>>>(x, T, out);
    gemm_bf16<<<dim3(MCOLS / 64, BATCH / 64), 256>>>(mh);
    pairwise_kernel<<<dim3(8, 4, OFEAT), 128>>>(mh, out);
}

// round 7
// speedup vs baseline: 3.3964x; 1.1712x over previous
#include <cuda_runtime.h>
#include <cuda_fp16.h>
#include <cuda_bf16.h>

#define BATCH   512
#define CIN     2048
#define OFEAT   64
#define KDIM    16
#define MCOLS   1024
#define OUTW    2112

// Scratch (device globals; no allocs)
__device__ __nv_bfloat16 g_xh[BATCH * CIN];     // 2 MB
__device__ __nv_bfloat16 g_Th[CIN * MCOLS];     // 4 MB
__device__ __half        g_mh[BATCH * MCOLS];   // 1 MB

// ---------------------------------------------------------------------------
// Prep: copy x -> out[:, :2048], zero out[:, 2048:], convert x,T -> bf16.
// 794624 float4 items, 4 per thread (MLP), 776 blocks x 256.
// ---------------------------------------------------------------------------
__global__ __launch_bounds__(256) void prep_kernel(
    const float* __restrict__ x, const float* __restrict__ T, float* __restrict__ out)
{
    const int base = blockIdx.x * 1024 + threadIdx.x;
#pragma unroll
    for (int it = 0; it < 4; ++it) {
        int id = base + it * 256;
        if (id < 262144) {                       // x: 512*512 float4
            int row = id >> 9, c4 = id & 511;
            float4 v = ((const float4*)&x[row * CIN])[c4];
            ((float4*)&out[row * OUTW])[c4] = v;
            __nv_bfloat162* dst = (__nv_bfloat162*)&g_xh[row * CIN + c4 * 4];
            dst[0] = __floats2bfloat162_rn(v.x, v.y);
            dst[1] = __floats2bfloat162_rn(v.z, v.w);
        } else if (id < 786432) {                // T: 2048*256 float4
            int i = id - 262144;
            float4 v = ((const float4*)T)[i];
            __nv_bfloat162* dst = (__nv_bfloat162*)&g_Th[i * 4];
            dst[0] = __floats2bfloat162_rn(v.x, v.y);
            dst[1] = __floats2bfloat162_rn(v.z, v.w);
        } else if (id < 794624) {                // zero tail: 512*16 float4
            int i = id - 786432;
            int row = i >> 4, c = i & 15;
            ((float4*)&out[row * OUTW + CIN])[c] = make_float4(0.f, 0.f, 0.f, 0.f);
        }
    }
}

// ---------------------------------------------------------------------------
// GEMM bf16: m = x @ T, mma.m16n8k16, 4-stage cp.async ring.
// Canonical order per stage: wait -> barrier -> issue(p+3) -> commit -> compute.
// BM=64 BN=64 BK=32, 256 thr (8 warps 2m x 4n, warp tile 32x16).
// ---------------------------------------------------------------------------
__device__ __forceinline__ void cp16(unsigned s, const void* g) {
    asm volatile("cp.async.cg.shared.global [%0], [%1], 16;" :: "r"(s), "l"(g));
}
#define CP_COMMIT()  asm volatile("cp.async.commit_group;")
#define CP_WAIT(N)   asm volatile("cp.async.wait_group %0;" :: "n"(N))

__device__ __forceinline__ void ldm_x4(unsigned* r, unsigned addr) {
    asm volatile("ldmatrix.sync.aligned.m8n8.x4.shared.b16 {%0,%1,%2,%3}, [%4];"
        : "=r"(r[0]), "=r"(r[1]), "=r"(r[2]), "=r"(r[3]) : "r"(addr));
}
__device__ __forceinline__ void ldm_x4t(unsigned* r, unsigned addr) {
    asm volatile("ldmatrix.sync.aligned.m8n8.x4.trans.shared.b16 {%0,%1,%2,%3}, [%4];"
        : "=r"(r[0]), "=r"(r[1]), "=r"(r[2]), "=r"(r[3]) : "r"(addr));
}
__device__ __forceinline__ void mma_bf16(float* d, const unsigned* a, const unsigned* b) {
    asm volatile(
        "mma.sync.aligned.m16n8k16.row.col.f32.bf16.bf16.f32 "
        "{%0,%1,%2,%3}, {%4,%5,%6,%7}, {%8,%9}, {%0,%1,%2,%3};\n"
        : "+f"(d[0]), "+f"(d[1]), "+f"(d[2]), "+f"(d[3])
        : "r"(a[0]), "r"(a[1]), "r"(a[2]), "r"(a[3]), "r"(b[0]), "r"(b[1]));
}

#define NSTAGE 4
#define NPANEL 64   // CIN / 32

__global__ __launch_bounds__(256) void gemm_bf16(__half* __restrict__ mh)
{
    __shared__ __nv_bfloat16 As[NSTAGE][64][40];   // 80B row stride
    __shared__ __nv_bfloat16 Bs[NSTAGE][32][72];   // 144B row stride

    const int tid  = threadIdx.x;
    const int lane = tid & 31;
    const int wid  = tid >> 5;
    const int wm   = wid & 1;
    const int wn   = wid >> 1;
    const int row0 = blockIdx.y * 64;
    const int col0 = blockIdx.x * 64;

    const int aRow = tid >> 2, aC = (tid & 3) * 8;   // A: 64x32, 1 cp16/thread
    const int bRow = tid >> 3, bC = (tid & 7) * 8;   // B: 32x64, 1 cp16/thread

    const __nv_bfloat16* gA = &g_xh[(row0 + aRow) * CIN + aC];
    const __nv_bfloat16* gB = &g_Th[bRow * MCOLS + col0 + bC];

    float d[2][2][4];
#pragma unroll
    for (int i = 0; i < 2; ++i)
#pragma unroll
        for (int j = 0; j < 2; ++j)
#pragma unroll
            for (int k = 0; k < 4; ++k) d[i][j][k] = 0.0f;

    // prologue: stages 0..2 (one commit group each)
#pragma unroll
    for (int s = 0; s < NSTAGE - 1; ++s) {
        cp16(__cvta_generic_to_shared(&As[s][aRow][aC]), gA + s * 32);
        cp16(__cvta_generic_to_shared(&Bs[s][bRow][bC]), gB + s * 32 * MCOLS);
        CP_COMMIT();
    }

    for (int p = 0; p < NPANEL; ++p) {
        CP_WAIT(NSTAGE - 2);     // my copies for stage p are complete
        __syncthreads();         // all threads' stage-p copies visible; all done with stage p-1
        if (p + NSTAGE - 1 < NPANEL) {   // overwrite buf (p-1)%4 with stage p+3
            const int s  = (p + NSTAGE - 1) & (NSTAGE - 1);
            const int k0 = (p + NSTAGE - 1) * 32;
            cp16(__cvta_generic_to_shared(&As[s][aRow][aC]), gA + k0);
            cp16(__cvta_generic_to_shared(&Bs[s][bRow][bC]), gB + k0 * MCOLS);
        }
        CP_COMMIT();             // empty group at tail keeps the count uniform
        const int buf = p & (NSTAGE - 1);

#pragma unroll
        for (int kk = 0; kk < 32; kk += 16) {
            unsigned a0[4], a1[4], bb[4];
            unsigned adrA0 = __cvta_generic_to_shared(
                &As[buf][wm * 32 + (lane & 15)][kk + (lane >> 4) * 8]);
            unsigned adrA1 = __cvta_generic_to_shared(
                &As[buf][wm * 32 + 16 + (lane & 15)][kk + (lane >> 4) * 8]);
            unsigned adrB = __cvta_generic_to_shared(
                &Bs[buf][kk + (lane & 15)][wn * 16 + (lane >> 4) * 8]);
            ldm_x4(a0, adrA0);
            ldm_x4(a1, adrA1);
            ldm_x4t(bb, adrB);
            mma_bf16(d[0][0], a0, bb);
            mma_bf16(d[0][1], a0, bb + 2);
            mma_bf16(d[1][0], a1, bb);
            mma_bf16(d[1][1], a1, bb + 2);
        }
    }

    // epilogue -> fp16
    const int g = lane >> 2, c = lane & 3;
#pragma unroll
    for (int ai = 0; ai < 2; ++ai)
#pragma unroll
        for (int bi = 0; bi < 2; ++bi) {
            int row = row0 + wm * 32 + ai * 16 + g;
            int col = col0 + wn * 16 + bi * 8 + c * 2;
            *(__half2*)&mh[row * MCOLS + col] =
                __floats2half2_rn(d[ai][bi][0], d[ai][bi][1]);
            *(__half2*)&mh[(row + 8) * MCOLS + col] =
                __floats2half2_rn(d[ai][bi][2], d[ai][bi][3]);
        }
}

// ---------------------------------------------------------------------------
// Pairwise: out[b, 2048+o] += sum_{j in chunk} exp(-L1(m[b,o,:], m[j,o,:]))
// grid (jc=8, bt=4, o=64), 128 thr. Screen processes 2 j per iter via half2
// over transposed group sums; full path only on warp-vote pass (diagonal).
// ---------------------------------------------------------------------------
__global__ __launch_bounds__(128) void pairwise_kernel(
    const __half* __restrict__ mh, float* __restrict__ out)
{
    __shared__ uint4  sjt[64][2];     // staged j rows (16 halves each)
    __shared__ __half sgT[4][64];     // transposed group sums

    const int jc  = blockIdx.x;
    const int bt  = blockIdx.y;
    const int o   = blockIdx.z;
    const int tid = threadIdx.x;
    const int b   = bt * 128 + tid;

    // own row -> 8 half2 regs + 4 broadcast group sums
    const uint4* vp = (const uint4*)&mh[b * MCOLS + o * KDIM];
    uint4 u0 = vp[0], u1 = vp[1];
    __half2 v[8];
    *(uint4*)&v[0] = u0;
    *(uint4*)&v[4] = u1;
    __half2 vgb[4];
    {
        __half2 t01 = __hadd2(v[0], v[1]);
        __half2 t23 = __hadd2(v[2], v[3]);
        __half2 t45 = __hadd2(v[4], v[5]);
        __half2 t67 = __hadd2(v[6], v[7]);
        vgb[0] = __half2half2(__hadd(__low2half(t01), __high2half(t01)));
        vgb[1] = __half2half2(__hadd(__low2half(t23), __high2half(t23)));
        vgb[2] = __half2half2(__hadd(__low2half(t45), __high2half(t45)));
        vgb[3] = __half2half2(__hadd(__low2half(t67), __high2half(t67)));
    }

    // stage j-chunk + transposed group sums
    if (tid < 64) {
        int j = jc * 64 + tid;
        const uint4* jp = (const uint4*)&mh[j * MCOLS + o * KDIM];
        uint4 w0 = jp[0], w1 = jp[1];
        sjt[tid][0] = w0;
        sjt[tid][1] = w1;
        __half2 s[8];
        *(uint4*)&s[0] = w0;
        *(uint4*)&s[4] = w1;
        __half2 a01 = __hadd2(s[0], s[1]);
        __half2 a23 = __hadd2(s[2], s[3]);
        __half2 a45 = __hadd2(s[4], s[5]);
        __half2 a67 = __hadd2(s[6], s[7]);
        sgT[0][tid] = __hadd(__low2half(a01), __high2half(a01));
        sgT[1][tid] = __hadd(__low2half(a23), __high2half(a23));
        sgT[2][tid] = __hadd(__low2half(a45), __high2half(a45));
        sgT[3][tid] = __hadd(__low2half(a67), __high2half(a67));
    }
    __syncthreads();

    float acc = 0.0f;
#pragma unroll 4
    for (int jp2 = 0; jp2 < 32; ++jp2) {
        // screen two j's at once: lanes of half2 = (j0, j1)
        __half2 e0 = __habs2(__hsub2(vgb[0], *(const __half2*)&sgT[0][jp2 * 2]));
        __half2 e1 = __habs2(__hsub2(vgb[1], *(const __half2*)&sgT[1][jp2 * 2]));
        __half2 e2 = __habs2(__hsub2(vgb[2], *(const __half2*)&sgT[2][jp2 * 2]));
        __half2 e3 = __habs2(__hsub2(vgb[3], *(const __half2*)&sgT[3][jp2 * 2]));
        __half2 et = __hadd2(__hadd2(e0, e1), __hadd2(e2, e3));
        float mn = __half2float(__hmin(__low2half(et), __high2half(et)));
        if (__any_sync(0xffffffffu, mn < 30.0f)) {
#pragma unroll
            for (int t = 0; t < 2; ++t) {
                const int jj = jp2 * 2 + t;
                __half2 s[8];
                *(uint4*)&s[0] = sjt[jj][0];
                *(uint4*)&s[4] = sjt[jj][1];
                __half2 q0 = __habs2(__hsub2(v[0], s[0]));
                __half2 q1 = __habs2(__hsub2(v[1], s[1]));
                __half2 q2 = __habs2(__hsub2(v[2], s[2]));
                __half2 q3 = __habs2(__hsub2(v[3], s[3]));
                __half2 q4 = __habs2(__hsub2(v[4], s[4]));
                __half2 q5 = __habs2(__hsub2(v[5], s[5]));
                __half2 q6 = __habs2(__hsub2(v[6], s[6]));
                __half2 q7 = __habs2(__hsub2(v[7], s[7]));
                __half2 sm = __hadd2(__hadd2(__hadd2(q0, q1), __hadd2(q2, q3)),
                                     __hadd2(__hadd2(q4, q5), __hadd2(q6, q7)));
                float dist = __low2float(sm) + __high2float(sm);
                acc += __expf(-dist);
            }
        }
    }

    atomicAdd(&out[b * OUTW + CIN + o], acc);
}

extern "C" void kernel_launch(void* const* d_in, const int* in_sizes, int n_in,
                              void* d_out, int out_size)
{
    const float* x = (const float*)d_in[0];
    const float* T = (const float*)d_in[1];
    float* out = (float*)d_out;

    __half* mh;
    cudaGetSymbolAddress((void**)&mh, g_mh);

    prep_kernel<<<776, 256>>>(x, T, out);
    gemm_bf16<<<dim3(MCOLS / 64, BATCH / 64), 256>>>(mh);
    pairwise_kernel<<<dim3(8, 4, OFEAT), 128>>>(mh, out);
}

// round 8
// speedup vs baseline: 3.5966x; 1.0589x over previous
#include <cuda_runtime.h>
#include <cuda_fp16.h>
#include <cuda_bf16.h>

#define BATCH   512
#define CIN     2048
#define OFEAT   64
#define KDIM    16
#define MCOLS   1024
#define OUTW    2112

// Scratch (device globals; no allocs)
__device__ __nv_bfloat16 g_xh[BATCH * CIN];     // 2 MB
__device__ __nv_bfloat16 g_Th[CIN * MCOLS];     // 4 MB
__device__ __half        g_mh[BATCH * MCOLS];   // 1 MB

// ---------------------------------------------------------------------------
// Prep: region chosen by blockIdx (no per-thread divergence), 1 float4/thread.
// blocks [0,1024): x copy+convert; [1024,3072): T convert; [3072,3104): zero.
// ---------------------------------------------------------------------------
__global__ __launch_bounds__(256) void prep_kernel(
    const float* __restrict__ x, const float* __restrict__ T, float* __restrict__ out)
{
    const int bid = blockIdx.x;
    if (bid < 1024) {                            // x: 512*512 float4
        int id = bid * 256 + threadIdx.x;
        int row = id >> 9, c4 = id & 511;
        float4 v = ((const float4*)&x[row * CIN])[c4];
        ((float4*)&out[row * OUTW])[c4] = v;
        __nv_bfloat162* dst = (__nv_bfloat162*)&g_xh[row * CIN + c4 * 4];
        dst[0] = __floats2bfloat162_rn(v.x, v.y);
        dst[1] = __floats2bfloat162_rn(v.z, v.w);
    } else if (bid < 3072) {                     // T: 2048*256 float4
        int i = (bid - 1024) * 256 + threadIdx.x;
        float4 v = ((const float4*)T)[i];
        __nv_bfloat162* dst = (__nv_bfloat162*)&g_Th[i * 4];
        dst[0] = __floats2bfloat162_rn(v.x, v.y);
        dst[1] = __floats2bfloat162_rn(v.z, v.w);
    } else {                                     // zero tail: 512*16 float4
        int i = (bid - 3072) * 256 + threadIdx.x;
        int row = i >> 4, c = i & 15;
        ((float4*)&out[row * OUTW + CIN])[c] = make_float4(0.f, 0.f, 0.f, 0.f);
    }
}

// ---------------------------------------------------------------------------
// GEMM bf16: m = x @ T, mma.m16n8k16, 4-stage cp.async ring.
// BM=32 BN=64 BK=32 -> grid 16x16 = 256 blocks, 2 CTAs/SM for latency hiding.
// 8 warps (2m x 4n), warp tile 16x16. Order: wait -> bar -> issue -> compute.
// ---------------------------------------------------------------------------
__device__ __forceinline__ void cp16(unsigned s, const void* g) {
    asm volatile("cp.async.cg.shared.global [%0], [%1], 16;" :: "r"(s), "l"(g));
}
#define CP_COMMIT()  asm volatile("cp.async.commit_group;")
#define CP_WAIT(N)   asm volatile("cp.async.wait_group %0;" :: "n"(N))

__device__ __forceinline__ void ldm_x4(unsigned* r, unsigned addr) {
    asm volatile("ldmatrix.sync.aligned.m8n8.x4.shared.b16 {%0,%1,%2,%3}, [%4];"
        : "=r"(r[0]), "=r"(r[1]), "=r"(r[2]), "=r"(r[3]) : "r"(addr));
}
__device__ __forceinline__ void ldm_x4t(unsigned* r, unsigned addr) {
    asm volatile("ldmatrix.sync.aligned.m8n8.x4.trans.shared.b16 {%0,%1,%2,%3}, [%4];"
        : "=r"(r[0]), "=r"(r[1]), "=r"(r[2]), "=r"(r[3]) : "r"(addr));
}
__device__ __forceinline__ void mma_bf16(float* d, const unsigned* a, const unsigned* b) {
    asm volatile(
        "mma.sync.aligned.m16n8k16.row.col.f32.bf16.bf16.f32 "
        "{%0,%1,%2,%3}, {%4,%5,%6,%7}, {%8,%9}, {%0,%1,%2,%3};\n"
        : "+f"(d[0]), "+f"(d[1]), "+f"(d[2]), "+f"(d[3])
        : "r"(a[0]), "r"(a[1]), "r"(a[2]), "r"(a[3]), "r"(b[0]), "r"(b[1]));
}

#define NSTAGE 4
#define NPANEL 64   // CIN / 32

__global__ __launch_bounds__(256, 2) void gemm_bf16(__half* __restrict__ mh)
{
    __shared__ __nv_bfloat16 As[NSTAGE][32][40];   // 80B row stride
    __shared__ __nv_bfloat16 Bs[NSTAGE][32][72];   // 144B row stride

    const int tid  = threadIdx.x;
    const int lane = tid & 31;
    const int wid  = tid >> 5;
    const int wm   = wid & 1;      // 2 m-tiles of 16
    const int wn   = wid >> 1;     // 4 n-tiles of 16
    const int row0 = blockIdx.y * 32;
    const int col0 = blockIdx.x * 64;

    // staging: B 32x64 (1 cp16/thread), A 32x32 (threads < 128, 1 cp16)
    const int bRow = tid >> 3, bC = (tid & 7) * 8;
    const int aRow = (tid & 127) >> 2, aC = (tid & 3) * 8;
    const bool doA = tid < 128;

    const __nv_bfloat16* gA = &g_xh[(row0 + aRow) * CIN + aC];
    const __nv_bfloat16* gB = &g_Th[bRow * MCOLS + col0 + bC];

    float d[2][4];
#pragma unroll
    for (int j = 0; j < 2; ++j)
#pragma unroll
        for (int k = 0; k < 4; ++k) d[j][k] = 0.0f;

    // prologue: stages 0..2
#pragma unroll
    for (int s = 0; s < NSTAGE - 1; ++s) {
        if (doA) cp16(__cvta_generic_to_shared(&As[s][aRow][aC]), gA + s * 32);
        cp16(__cvta_generic_to_shared(&Bs[s][bRow][bC]), gB + s * 32 * MCOLS);
        CP_COMMIT();
    }

    for (int p = 0; p < NPANEL; ++p) {
        CP_WAIT(NSTAGE - 2);     // my stage-p copies complete
        __syncthreads();         // all copies visible; all threads done with p-1
        if (p + NSTAGE - 1 < NPANEL) {
            const int s  = (p + NSTAGE - 1) & (NSTAGE - 1);
            const int k0 = (p + NSTAGE - 1) * 32;
            if (doA) cp16(__cvta_generic_to_shared(&As[s][aRow][aC]), gA + k0);
            cp16(__cvta_generic_to_shared(&Bs[s][bRow][bC]), gB + k0 * MCOLS);
        }
        CP_COMMIT();
        const int buf = p & (NSTAGE - 1);

#pragma unroll
        for (int kk = 0; kk < 32; kk += 16) {
            unsigned a[4], bb[4];
            unsigned adrA = __cvta_generic_to_shared(
                &As[buf][wm * 16 + (lane & 15)][kk + (lane >> 4) * 8]);
            unsigned adrB = __cvta_generic_to_shared(
                &Bs[buf][kk + (lane & 15)][wn * 16 + (lane >> 4) * 8]);
            ldm_x4(a, adrA);
            ldm_x4t(bb, adrB);
            mma_bf16(d[0], a, bb);
            mma_bf16(d[1], a, bb + 2);
        }
    }

    // epilogue -> fp16
    const int g = lane >> 2, c = lane & 3;
#pragma unroll
    for (int bi = 0; bi < 2; ++bi) {
        int row = row0 + wm * 16 + g;
        int col = col0 + wn * 16 + bi * 8 + c * 2;
        *(__half2*)&mh[row * MCOLS + col]       = __floats2half2_rn(d[bi][0], d[bi][1]);
        *(__half2*)&mh[(row + 8) * MCOLS + col] = __floats2half2_rn(d[bi][2], d[bi][3]);
    }
}

// ---------------------------------------------------------------------------
// Pairwise: out[b, 2048+o] += sum_{j in chunk} exp(-L1(m[b,o,:], m[j,o,:]))
// grid (jc=8, bt=4, o=64), 128 thr. Screen 2 j/iter via half2 group sums;
// full path only on warp-vote pass (diagonal chunk).
// ---------------------------------------------------------------------------
__global__ __launch_bounds__(128) void pairwise_kernel(
    const __half* __restrict__ mh, float* __restrict__ out)
{
    __shared__ uint4  sjt[64][2];     // staged j rows (16 halves each)
    __shared__ __half sgT[4][64];     // transposed group sums

    const int jc  = blockIdx.x;
    const int bt  = blockIdx.y;
    const int o   = blockIdx.z;
    const int tid = threadIdx.x;
    const int b   = bt * 128 + tid;

    const uint4* vp = (const uint4*)&mh[b * MCOLS + o * KDIM];
    uint4 u0 = vp[0], u1 = vp[1];
    __half2 v[8];
    *(uint4*)&v[0] = u0;
    *(uint4*)&v[4] = u1;
    __half2 vgb[4];
    {
        __half2 t01 = __hadd2(v[0], v[1]);
        __half2 t23 = __hadd2(v[2], v[3]);
        __half2 t45 = __hadd2(v[4], v[5]);
        __half2 t67 = __hadd2(v[6], v[7]);
        vgb[0] = __half2half2(__hadd(__low2half(t01), __high2half(t01)));
        vgb[1] = __half2half2(__hadd(__low2half(t23), __high2half(t23)));
        vgb[2] = __half2half2(__hadd(__low2half(t45), __high2half(t45)));
        vgb[3] = __half2half2(__hadd(__low2half(t67), __high2half(t67)));
    }

    if (tid < 64) {
        int j = jc * 64 + tid;
        const uint4* jp = (const uint4*)&mh[j * MCOLS + o * KDIM];
        uint4 w0 = jp[0], w1 = jp[1];
        sjt[tid][0] = w0;
        sjt[tid][1] = w1;
        __half2 s[8];
        *(uint4*)&s[0] = w0;
        *(uint4*)&s[4] = w1;
        __half2 a01 = __hadd2(s[0], s[1]);
        __half2 a23 = __hadd2(s[2], s[3]);
        __half2 a45 = __hadd2(s[4], s[5]);
        __half2 a67 = __hadd2(s[6], s[7]);
        sgT[0][tid] = __hadd(__low2half(a01), __high2half(a01));
        sgT[1][tid] = __hadd(__low2half(a23), __high2half(a23));
        sgT[2][tid] = __hadd(__low2half(a45), __high2half(a45));
        sgT[3][tid] = __hadd(__low2half(a67), __high2half(a67));
    }
    __syncthreads();

    float acc = 0.0f;
#pragma unroll 4
    for (int jp2 = 0; jp2 < 32; ++jp2) {
        __half2 e0 = __habs2(__hsub2(vgb[0], *(const __half2*)&sgT[0][jp2 * 2]));
        __half2 e1 = __habs2(__hsub2(vgb[1], *(const __half2*)&sgT[1][jp2 * 2]));
        __half2 e2 = __habs2(__hsub2(vgb[2], *(const __half2*)&sgT[2][jp2 * 2]));
        __half2 e3 = __habs2(__hsub2(vgb[3], *(const __half2*)&sgT[3][jp2 * 2]));
        __half2 et = __hadd2(__hadd2(e0, e1), __hadd2(e2, e3));
        float mn = __half2float(__hmin(__low2half(et), __high2half(et)));
        if (__any_sync(0xffffffffu, mn < 30.0f)) {
#pragma unroll
            for (int t = 0; t < 2; ++t) {
                const int jj = jp2 * 2 + t;
                __half2 s[8];
                *(uint4*)&s[0] = sjt[jj][0];
                *(uint4*)&s[4] = sjt[jj][1];
                __half2 q0 = __habs2(__hsub2(v[0], s[0]));
                __half2 q1 = __habs2(__hsub2(v[1], s[1]));
                __half2 q2 = __habs2(__hsub2(v[2], s[2]));
                __half2 q3 = __habs2(__hsub2(v[3], s[3]));
                __half2 q4 = __habs2(__hsub2(v[4], s[4]));
                __half2 q5 = __habs2(__hsub2(v[5], s[5]));
                __half2 q6 = __habs2(__hsub2(v[6], s[6]));
                __half2 q7 = __habs2(__hsub2(v[7], s[7]));
                __half2 sm = __hadd2(__hadd2(__hadd2(q0, q1), __hadd2(q2, q3)),
                                     __hadd2(__hadd2(q4, q5), __hadd2(q6, q7)));
                float dist = __low2float(sm) + __high2float(sm);
                acc += __expf(-dist);
            }
        }
    }

    atomicAdd(&out[b * OUTW + CIN + o], acc);
}

extern "C" void kernel_launch(void* const* d_in, const int* in_sizes, int n_in,
                              void* d_out, int out_size)
{
    const float* x = (const float*)d_in[0];
    const float* T = (const float*)d_in[1];
    float* out = (float*)d_out;

    __half* mh;
    cudaGetSymbolAddress((void**)&mh, g_mh);

    prep_kernel<<<3104, 256>>>(x, T, out);
    gemm_bf16<<<dim3(MCOLS / 64, BATCH / 32), 256>>>(mh);
    pairwise_kernel<<<dim3(8, 4, OFEAT), 128>>>(mh, out);
}

// round 9
// speedup vs baseline: 3.8181x; 1.0616x over previous
#include <cuda_runtime.h>
#include <cuda_fp16.h>
#include <cuda_bf16.h>

#define BATCH   512
#define CIN     2048
#define OFEAT   64
#define KDIM    16
#define MCOLS   1024
#define OUTW    2112

// Scratch (device globals; no allocs)
__device__ __nv_bfloat16 g_xh[BATCH * CIN];     // 2 MB
__device__ __nv_bfloat16 g_Th[CIN * MCOLS];     // 4 MB
__device__ __half        g_mh[BATCH * MCOLS];   // 1 MB

// ---------------------------------------------------------------------------
// Prep: convert x,T -> bf16 and zero out[:, 2048:]. Region by blockIdx.
// blocks [0,1024): x conv; [1024,3072): T conv; [3072,3104): zero tail.
// (x -> out copy is folded into pairwise_kernel.)
// ---------------------------------------------------------------------------
__global__ __launch_bounds__(256) void prep_kernel(
    const float* __restrict__ x, const float* __restrict__ T, float* __restrict__ out)
{
    const int bid = blockIdx.x;
    if (bid < 1024) {                            // x: 512*512 float4
        int id = bid * 256 + threadIdx.x;
        float4 v = ((const float4*)x)[id];
        __nv_bfloat162* dst = (__nv_bfloat162*)&g_xh[id * 4];
        dst[0] = __floats2bfloat162_rn(v.x, v.y);
        dst[1] = __floats2bfloat162_rn(v.z, v.w);
    } else if (bid < 3072) {                     // T: 2048*256 float4
        int i = (bid - 1024) * 256 + threadIdx.x;
        float4 v = ((const float4*)T)[i];
        __nv_bfloat162* dst = (__nv_bfloat162*)&g_Th[i * 4];
        dst[0] = __floats2bfloat162_rn(v.x, v.y);
        dst[1] = __floats2bfloat162_rn(v.z, v.w);
    } else {                                     // zero tail: 512*16 float4
        int i = (bid - 3072) * 256 + threadIdx.x;
        int row = i >> 4, c = i & 15;
        ((float4*)&out[row * OUTW + CIN])[c] = make_float4(0.f, 0.f, 0.f, 0.f);
    }
}

// ---------------------------------------------------------------------------
// GEMM bf16: m = x @ T, mma.m16n8k16, 4-stage cp.async ring.
// BM=32 BN=64 BK=32, 128 threads (4 warps, 2m x 2n, warp tile 16x32).
// grid 16x16 = 256 blocks; small CTAs -> many resident/SM for latency hiding.
// ---------------------------------------------------------------------------
__device__ __forceinline__ void cp16(unsigned s, const void* g) {
    asm volatile("cp.async.cg.shared.global [%0], [%1], 16;" :: "r"(s), "l"(g));
}
#define CP_COMMIT()  asm volatile("cp.async.commit_group;")
#define CP_WAIT(N)   asm volatile("cp.async.wait_group %0;" :: "n"(N))

__device__ __forceinline__ void ldm_x4(unsigned* r, unsigned addr) {
    asm volatile("ldmatrix.sync.aligned.m8n8.x4.shared.b16 {%0,%1,%2,%3}, [%4];"
        : "=r"(r[0]), "=r"(r[1]), "=r"(r[2]), "=r"(r[3]) : "r"(addr));
}
__device__ __forceinline__ void ldm_x4t(unsigned* r, unsigned addr) {
    asm volatile("ldmatrix.sync.aligned.m8n8.x4.trans.shared.b16 {%0,%1,%2,%3}, [%4];"
        : "=r"(r[0]), "=r"(r[1]), "=r"(r[2]), "=r"(r[3]) : "r"(addr));
}
__device__ __forceinline__ void mma_bf16(float* d, const unsigned* a, const unsigned* b) {
    asm volatile(
        "mma.sync.aligned.m16n8k16.row.col.f32.bf16.bf16.f32 "
        "{%0,%1,%2,%3}, {%4,%5,%6,%7}, {%8,%9}, {%0,%1,%2,%3};\n"
        : "+f"(d[0]), "+f"(d[1]), "+f"(d[2]), "+f"(d[3])
        : "r"(a[0]), "r"(a[1]), "r"(a[2]), "r"(a[3]), "r"(b[0]), "r"(b[1]));
}

#define NSTAGE 4
#define NPANEL 64   // CIN / 32

__global__ __launch_bounds__(128) void gemm_bf16(__half* __restrict__ mh)
{
    __shared__ __nv_bfloat16 As[NSTAGE][32][40];   // 80B row stride
    __shared__ __nv_bfloat16 Bs[NSTAGE][32][72];   // 144B row stride

    const int tid  = threadIdx.x;
    const int lane = tid & 31;
    const int wid  = tid >> 5;
    const int wm   = wid & 1;      // 2 m-warps of 16
    const int wn   = wid >> 1;     // 2 n-warps of 32
    const int row0 = blockIdx.y * 32;
    const int col0 = blockIdx.x * 64;

    // staging: A 32x32 (1 cp16/thread), B 32x64 (2 cp16/thread)
    const int aRow = tid >> 2, aC = (tid & 3) * 8;
    const int bRow = tid >> 2, bC = (tid & 3) * 16;

    const __nv_bfloat16* gA = &g_xh[(row0 + aRow) * CIN + aC];
    const __nv_bfloat16* gB = &g_Th[bRow * MCOLS + col0 + bC];

    float d[2][2][4];
#pragma unroll
    for (int i = 0; i < 2; ++i)
#pragma unroll
        for (int j = 0; j < 2; ++j)
#pragma unroll
            for (int k = 0; k < 4; ++k) d[i][j][k] = 0.0f;

    // prologue: stages 0..2
#pragma unroll
    for (int s = 0; s < NSTAGE - 1; ++s) {
        cp16(__cvta_generic_to_shared(&As[s][aRow][aC]), gA + s * 32);
        cp16(__cvta_generic_to_shared(&Bs[s][bRow][bC]),     gB + s * 32 * MCOLS);
        cp16(__cvta_generic_to_shared(&Bs[s][bRow][bC + 8]), gB + s * 32 * MCOLS + 8);
        CP_COMMIT();
    }

    for (int p = 0; p < NPANEL; ++p) {
        CP_WAIT(NSTAGE - 2);     // my stage-p copies complete
        __syncthreads();         // all copies visible; all threads done with p-1
        if (p + NSTAGE - 1 < NPANEL) {
            const int s  = (p + NSTAGE - 1) & (NSTAGE - 1);
            const int k0 = (p + NSTAGE - 1) * 32;
            cp16(__cvta_generic_to_shared(&As[s][aRow][aC]), gA + k0);
            cp16(__cvta_generic_to_shared(&Bs[s][bRow][bC]),     gB + k0 * MCOLS);
            cp16(__cvta_generic_to_shared(&Bs[s][bRow][bC + 8]), gB + k0 * MCOLS + 8);
        }
        CP_COMMIT();
        const int buf = p & (NSTAGE - 1);

#pragma unroll
        for (int kk = 0; kk < 32; kk += 16) {
            unsigned a[4];
            unsigned adrA = __cvta_generic_to_shared(
                &As[buf][wm * 16 + (lane & 15)][kk + (lane >> 4) * 8]);
            ldm_x4(a, adrA);
#pragma unroll
            for (int bi = 0; bi < 2; ++bi) {
                unsigned bb[4];
                unsigned adrB = __cvta_generic_to_shared(
                    &Bs[buf][kk + (lane & 15)][wn * 32 + bi * 16 + (lane >> 4) * 8]);
                ldm_x4t(bb, adrB);
                mma_bf16(d[bi][0], a, bb);
                mma_bf16(d[bi][1], a, bb + 2);
            }
        }
    }

    // epilogue -> fp16
    const int g = lane >> 2, c = lane & 3;
#pragma unroll
    for (int bi = 0; bi < 2; ++bi)
#pragma unroll
        for (int h = 0; h < 2; ++h) {
            int row = row0 + wm * 16 + g;
            int col = col0 + wn * 32 + bi * 16 + h * 8 + c * 2;
            *(__half2*)&mh[row * MCOLS + col] =
                __floats2half2_rn(d[bi][h][0], d[bi][h][1]);
            *(__half2*)&mh[(row + 8) * MCOLS + col] =
                __floats2half2_rn(d[bi][h][2], d[bi][h][3]);
        }
}

// ---------------------------------------------------------------------------
// Pairwise: out[b, 2048+o] += sum_{j in chunk} exp(-L1(m[b,o,:], m[j,o,:]))
// grid (jc=8, bt=4, o=64) = 2048 blocks x 128 thr. Also folds the x -> out
// copy: exactly one float4 per thread (2048*128 = 512*512).
// ---------------------------------------------------------------------------
__global__ __launch_bounds__(128) void pairwise_kernel(
    const __half* __restrict__ mh, const float* __restrict__ x, float* __restrict__ out)
{
    __shared__ uint4  sjt[64][2];     // staged j rows (16 halves each)
    __shared__ __half sgT[4][64];     // transposed group sums

    const int jc  = blockIdx.x;
    const int bt  = blockIdx.y;
    const int o   = blockIdx.z;
    const int tid = threadIdx.x;
    const int b   = bt * 128 + tid;

    // folded x -> out copy: one float4 per thread
    {
        int id  = ((o * 4 + bt) * 8 + jc) * 128 + tid;   // 0..262143
        int row = id >> 9, c4 = id & 511;
        ((float4*)&out[row * OUTW])[c4] = ((const float4*)&x[row * CIN])[c4];
    }

    const uint4* vp = (const uint4*)&mh[b * MCOLS + o * KDIM];
    uint4 u0 = vp[0], u1 = vp[1];
    __half2 v[8];
    *(uint4*)&v[0] = u0;
    *(uint4*)&v[4] = u1;
    __half2 vgb[4];
    {
        __half2 t01 = __hadd2(v[0], v[1]);
        __half2 t23 = __hadd2(v[2], v[3]);
        __half2 t45 = __hadd2(v[4], v[5]);
        __half2 t67 = __hadd2(v[6], v[7]);
        vgb[0] = __half2half2(__hadd(__low2half(t01), __high2half(t01)));
        vgb[1] = __half2half2(__hadd(__low2half(t23), __high2half(t23)));
        vgb[2] = __half2half2(__hadd(__low2half(t45), __high2half(t45)));
        vgb[3] = __half2half2(__hadd(__low2half(t67), __high2half(t67)));
    }

    if (tid < 64) {
        int j = jc * 64 + tid;
        const uint4* jp = (const uint4*)&mh[j * MCOLS + o * KDIM];
        uint4 w0 = jp[0], w1 = jp[1];
        sjt[tid][0] = w0;
        sjt[tid][1] = w1;
        __half2 s[8];
        *(uint4*)&s[0] = w0;
        *(uint4*)&s[4] = w1;
        __half2 a01 = __hadd2(s[0], s[1]);
        __half2 a23 = __hadd2(s[2], s[3]);
        __half2 a45 = __hadd2(s[4], s[5]);
        __half2 a67 = __hadd2(s[6], s[7]);
        sgT[0][tid] = __hadd(__low2half(a01), __high2half(a01));
        sgT[1][tid] = __hadd(__low2half(a23), __high2half(a23));
        sgT[2][tid] = __hadd(__low2half(a45), __high2half(a45));
        sgT[3][tid] = __hadd(__low2half(a67), __high2half(a67));
    }
    __syncthreads();

    float acc = 0.0f;
#pragma unroll 4
    for (int jp2 = 0; jp2 < 32; ++jp2) {
        __half2 e0 = __habs2(__hsub2(vgb[0], *(const __half2*)&sgT[0][jp2 * 2]));
        __half2 e1 = __habs2(__hsub2(vgb[1], *(const __half2*)&sgT[1][jp2 * 2]));
        __half2 e2 = __habs2(__hsub2(vgb[2], *(const __half2*)&sgT[2][jp2 * 2]));
        __half2 e3 = __habs2(__hsub2(vgb[3], *(const __half2*)&sgT[3][jp2 * 2]));
        __half2 et = __hadd2(__hadd2(e0, e1), __hadd2(e2, e3));
        float mn = __half2float(__hmin(__low2half(et), __high2half(et)));
        if (__any_sync(0xffffffffu, mn < 30.0f)) {
#pragma unroll
            for (int t = 0; t < 2; ++t) {
                const int jj = jp2 * 2 + t;
                __half2 s[8];
                *(uint4*)&s[0] = sjt[jj][0];
                *(uint4*)&s[4] = sjt[jj][1];
                __half2 q0 = __habs2(__hsub2(v[0], s[0]));
                __half2 q1 = __habs2(__hsub2(v[1], s[1]));
                __half2 q2 = __habs2(__hsub2(v[2], s[2]));
                __half2 q3 = __habs2(__hsub2(v[3], s[3]));
                __half2 q4 = __habs2(__hsub2(v[4], s[4]));
                __half2 q5 = __habs2(__hsub2(v[5], s[5]));
                __half2 q6 = __habs2(__hsub2(v[6], s[6]));
                __half2 q7 = __habs2(__hsub2(v[7], s[7]));
                __half2 sm = __hadd2(__hadd2(__hadd2(q0, q1), __hadd2(q2, q3)),
                                     __hadd2(__hadd2(q4, q5), __hadd2(q6, q7)));
                float dist = __low2float(sm) + __high2float(sm);
                acc += __expf(-dist);
            }
        }
    }

    atomicAdd(&out[b * OUTW + CIN + o], acc);
}

extern "C" void kernel_launch(void* const* d_in, const int* in_sizes, int n_in,
                              void* d_out, int out_size)
{
    const float* x = (const float*)d_in[0];
    const float* T = (const float*)d_in[1];
    float* out = (float*)d_out;

    __half* mh;
    cudaGetSymbolAddress((void**)&mh, g_mh);

    prep_kernel<<<3104, 256>>>(x, T, out);
    gemm_bf16<<<dim3(MCOLS / 64, BATCH / 32), 128>>>(mh);
    pairwise_kernel<<<dim3(8, 4, OFEAT), 128>>>(mh, x, out);
}